// round 9
// baseline (speedup 1.0000x reference)
#include <cuda_runtime.h>
#include <cuda_bf16.h>
#include <cstdint>

// ===========================================================================
// PackedSirenExperts via mma.sync m16n8k16 bf16 (portable PTX, compute_103).
// R9 = R8 with the blob row-stride bug fixed (rows are 64B: hi|lo fused per
// q-block; prep and B-load now both use 64B stride).
//  - warp tile 64x64 (4 warps = 4 n-quarters, each covers all 64 rows):
//    B fragments reused across 4 m-frags; one LDS.128 per n per slab gives
//    {bh.x,bh.y,bl.x,bl.y}.
//  - warp-PRIVATE B staging (cp.async own o-quarter): no per-slab barriers,
//    just cp.async.wait_group 0 + __syncwarp; 2 __syncthreads per layer.
//  - co-resident CTA dephasing (~3000 cyc skew for slot-B CTAs).
// 3-term bf16 split (fp32 accum): D += Ahi*Whi + Alo*Whi + Ahi*Wlo.
// CTA = (expert, 64 rows), 128 thr; 2 CTAs/SM (112.4 KB smem).
// ===========================================================================

namespace {
constexpr int Mexp = 64;
constexpr int Bdim = 8192;
constexpr float W0F = 30.0f;

constexpr int OFF_AHI  = 0;          // 64 rows x 512B swizzled bf16 (32K)
constexpr int OFF_ALO  = 32768;      // 32K
constexpr int OFF_WBUF = 65536;      // 2 x 16384 (double-buffered k16 slab)
constexpr int OFF_W0   = 98304;      // 768 f
constexpr int OFF_WF   = 101376;     // 768 f
constexpr int OFF_B0   = 104448;     // 256 f
constexpr int OFF_B123 = 105472;     // 768 f
constexpr int OFF_X    = 108544;     // 192 f
constexpr int OFF_PBUF = 109312;     // 768 f (4 quarters x 64 rows x 3)
constexpr int SMEM_TOTAL = 112384;
}

// prepped weights: slab blob = [m][layer*16 + s] of 16KB, laid out as
// 4 o-quarters (wn) x 64 o-rows x 64B; row = 4 q-blocks of 16B:
//   {hi(k=2q,2q+1), hi(k=2q+8,2q+9), lo(k=2q,2q+1), lo(k=2q+8,2q+9)}
__device__ __align__(16) unsigned char g_wp[(size_t)Mexp * 48 * 16384];

// ---------------------------------------------------------------------------
__device__ __forceinline__ uint32_t smem_u32(const void* p) {
    uint32_t a;
    asm("{ .reg .u64 t; cvta.to.shared.u64 t, %1; cvt.u32.u64 %0, t; }" : "=r"(a) : "l"(p));
    return a;
}
__device__ __forceinline__ void cp16(uint32_t s, const void* g) {
    asm volatile("cp.async.cg.shared.global [%0], [%1], 16;" :: "r"(s), "l"(g));
}
__device__ __forceinline__ void cp_commit() { asm volatile("cp.async.commit_group;"); }
__device__ __forceinline__ void cp_wait0() {
    asm volatile("cp.async.wait_group 0;" ::: "memory");
}
__device__ __forceinline__ uint32_t pack2(float v0, float v1) {
    __nv_bfloat162 t = __floats2bfloat162_rn(v0, v1);
    return *reinterpret_cast<uint32_t*>(&t);
}
__device__ __forceinline__ uint32_t pack2lo(float v0, float v1) {
    __nv_bfloat16 h0 = __float2bfloat16(v0);
    __nv_bfloat16 h1 = __float2bfloat16(v1);
    __nv_bfloat162 t = __floats2bfloat162_rn(v0 - __bfloat162float(h0),
                                             v1 - __bfloat162float(h1));
    return *reinterpret_cast<uint32_t*>(&t);
}
// A swizzled byte offset: row r (0..63), col k (0..255) bf16
__device__ __forceinline__ uint32_t aoff(int r, int k) {
    return (uint32_t)(r * 512 + ((((k >> 3) ^ (r & 7)) << 4) | ((k & 7) * 2)));
}
__device__ __forceinline__ void mma16816(float* d, const uint32_t* a,
                                         uint32_t b0, uint32_t b1) {
    asm volatile(
        "mma.sync.aligned.m16n8k16.row.col.f32.bf16.bf16.f32 "
        "{%0,%1,%2,%3}, {%4,%5,%6,%7}, {%8,%9}, {%0,%1,%2,%3};"
        : "+f"(d[0]), "+f"(d[1]), "+f"(d[2]), "+f"(d[3])
        : "r"(a[0]), "r"(a[1]), "r"(a[2]), "r"(a[3]), "r"(b0), "r"(b1));
}
__device__ __forceinline__ void ldsm4(uint32_t* r, uint32_t addr) {
    asm volatile("ldmatrix.sync.aligned.m8n8.x4.shared.b16 {%0,%1,%2,%3}, [%4];"
                 : "=r"(r[0]), "=r"(r[1]), "=r"(r[2]), "=r"(r[3]) : "r"(addr));
}

// ---------------------------------------------------------------------------
// Prep: fp32 W[m][o][i] -> k16-slab blobs, quarter-major, 64B rows,
// hi|lo fused per q-block. One thread per (m, slab, o).
// ---------------------------------------------------------------------------
__global__ void prep_weights(const float* __restrict__ w, int layer) {
    int id = blockIdx.x * blockDim.x + threadIdx.x;   // 262144
    int o = id & 255;
    int s = (id >> 8) & 15;
    int m = id >> 12;
    const float* src = w + ((size_t)m * 256 + o) * 256 + s * 16;
    unsigned char* dst = g_wp + (size_t)(m * 48 + layer * 16 + s) * 16384
                       + (o >> 6) * 4096 + (o & 63) * 64;    // 64B row stride
#pragma unroll
    for (int q = 0; q < 4; q++) {
        float f0 = src[2 * q],     f1 = src[2 * q + 1];
        float f2 = src[2 * q + 8], f3 = src[2 * q + 9];
        uint4 v;
        v.x = pack2(f0, f1);   v.y = pack2(f2, f3);
        v.z = pack2lo(f0, f1); v.w = pack2lo(f2, f3);
        *reinterpret_cast<uint4*>(dst + q * 16) = v;
    }
}

// ---------------------------------------------------------------------------
// Main kernel. grid = Mexp*128 = 8192 CTAs (expert-major), 128 threads.
// ---------------------------------------------------------------------------
__global__ void __launch_bounds__(128, 2)
siren_mma(const float* __restrict__ x,
          const float* __restrict__ w0, const float* __restrict__ b0,
          const float* __restrict__ b1, const float* __restrict__ b2,
          const float* __restrict__ b3,
          const float* __restrict__ wf, const float* __restrict__ bf,
          float* __restrict__ out) {
    extern __shared__ __align__(16) unsigned char smem[];
    const uint32_t sb = smem_u32(smem);
    float* w0s  = reinterpret_cast<float*>(smem + OFF_W0);
    float* wfs  = reinterpret_cast<float*>(smem + OFF_WF);
    float* b0s  = reinterpret_cast<float*>(smem + OFF_B0);
    float* b123 = reinterpret_cast<float*>(smem + OFF_B123);
    float* xs   = reinterpret_cast<float*>(smem + OFF_X);
    float* pbuf = reinterpret_cast<float*>(smem + OFF_PBUF);

    const int tid  = threadIdx.x;
    const int lane = tid & 31;
    const int wn   = tid >> 5;         // warp = n-quarter: cols wn*64..+63
    const int rl   = lane >> 2;        // 0..7
    const int q    = lane & 3;         // 0..3
    const int m    = blockIdx.x >> 7;
    const int bt   = blockIdx.x & 127;
    const int row0 = bt * 64;
    const int lrow  = lane & 15;
    const int lhalf = lane >> 4;

    const unsigned char* wpm = g_wp + (size_t)m * 48 * 16384;

    // ---- prefetch slab 0 (own warp quarter: 4KB) ----
    {
        uint32_t dst = sb + OFF_WBUF + (uint32_t)(wn * 4096 + lane * 16);
        const unsigned char* src = wpm + wn * 4096 + lane * 16;
#pragma unroll
        for (int i = 0; i < 8; i++) cp16(dst + i * 512, src + i * 512);
        cp_commit();
    }

    // ---- stage small tensors ----
    for (int i = tid; i < 768; i += 128) w0s[i] = w0[m * 768 + i];
    for (int i = tid; i < 768; i += 128) wfs[i] = wf[m * 768 + i];
    for (int i = tid; i < 256; i += 128) {
        b0s[i]        = b0[m * 256 + i];
        b123[i]       = b1[m * 256 + i];
        b123[256 + i] = b2[m * 256 + i];
        b123[512 + i] = b3[m * 256 + i];
    }
    for (int i = tid; i < 192; i += 128) xs[i] = x[(size_t)row0 * 3 + i];
    __syncthreads();

    // ---- dephase co-resident CTA pairs (slot-B CTAs skew ~3000 cyc) ----
    if ((blockIdx.x / 148) & 1) {
        long long t0 = clock64();
        while (clock64() - t0 < 3000) { }
    }

    // ---- layer 0: warp covers cols [wn*64,+64), all 64 rows ----
    {
        const int cbase = wn * 64;
#pragma unroll 4
        for (int i = 0; i < 64; i++) {
            int pid = i * 32 + lane;
            int r  = pid & 63;
            int c  = cbase + (pid >> 6) * 2;
            float x0 = xs[r * 3], x1 = xs[r * 3 + 1], x2 = xs[r * 3 + 2];
            float p0 = fmaf(x2, w0s[c * 3 + 2], fmaf(x1, w0s[c * 3 + 1],
                       fmaf(x0, w0s[c * 3 + 0], b0s[c])));
            float p1 = fmaf(x2, w0s[c * 3 + 5], fmaf(x1, w0s[c * 3 + 4],
                       fmaf(x0, w0s[c * 3 + 3], b0s[c + 1])));
            float v0 = __sinf(W0F * p0);
            float v1 = __sinf(W0F * p1);
            uint32_t ao = aoff(r, c);
            *reinterpret_cast<uint32_t*>(smem + OFF_AHI + ao) = pack2(v0, v1);
            *reinterpret_cast<uint32_t*>(smem + OFF_ALO + ao) = pack2lo(v0, v1);
        }
    }
    __syncthreads();

    // ---- 3 hidden layers over 48 k16 weight slabs ----
    int t = 0;
#pragma unroll 1
    for (int L = 0; L < 3; L++) {
        float acc[8][4][4];               // [n][f][v]
#pragma unroll
        for (int n = 0; n < 8; n++)
#pragma unroll
            for (int f = 0; f < 4; f++)
#pragma unroll
                for (int v = 0; v < 4; v++) acc[n][f][v] = 0.0f;

        uint32_t ah[4][4], al[4][4];

#pragma unroll 1
        for (int s = 0; s < 16; s++, t++) {
            cp_wait0();
            __syncwarp();
            if (t < 47) {
                uint32_t dst = sb + OFF_WBUF + ((t + 1) & 1) * 16384
                             + (uint32_t)(wn * 4096 + lane * 16);
                const unsigned char* src = wpm + (size_t)(t + 1) * 16384
                                         + wn * 4096 + lane * 16;
#pragma unroll
                for (int i = 0; i < 8; i++) cp16(dst + i * 512, src + i * 512);
                cp_commit();
            }
            const unsigned char* wb = smem + OFF_WBUF + (t & 1) * 16384 + wn * 4096;

            // B fragments: 8 x LDS.128 {bh.x,bh.y,bl.x,bl.y}, 64B rows
            uint4 bq[8];
#pragma unroll
            for (int n = 0; n < 8; n++)
                bq[n] = *reinterpret_cast<const uint4*>(wb + (n * 8 + rl) * 64 + q * 16);

            // A fragments: f=0..3, hi & lo via ldmatrix.x4
            {
                int c3 = s * 2 + lhalf;
#pragma unroll
                for (int f = 0; f < 4; f++) {
                    int row = f * 16 + lrow;
                    uint32_t ad = sb + (uint32_t)(row * 512 + ((c3 ^ (row & 7)) << 4));
                    ldsm4(ah[f], ad);
                    ldsm4(al[f], ad + 32768);
                }
            }

            // pass 1: Ahi * Whi
#pragma unroll
            for (int n = 0; n < 8; n++)
#pragma unroll
                for (int f = 0; f < 4; f++)
                    mma16816(acc[n][f], ah[f], bq[n].x, bq[n].y);
            // pass 2: Alo * Whi
#pragma unroll
            for (int n = 0; n < 8; n++)
#pragma unroll
                for (int f = 0; f < 4; f++)
                    mma16816(acc[n][f], al[f], bq[n].x, bq[n].y);
            // pass 3: Ahi * Wlo
#pragma unroll
            for (int n = 0; n < 8; n++)
#pragma unroll
                for (int f = 0; f < 4; f++)
                    mma16816(acc[n][f], ah[f], bq[n].z, bq[n].w);
        }

        __syncthreads();   // all warps done reading A before overwrite

        if (L < 2) {
            const float* bl = b123 + L * 256;
#pragma unroll
            for (int n = 0; n < 8; n++) {
#pragma unroll
                for (int f = 0; f < 4; f++) {
                    int r   = f * 16 + rl;
                    int col = wn * 64 + n * 8 + q * 2;
                    float bb0 = bl[col], bb1 = bl[col + 1];
                    float v0 = __sinf(W0F * (acc[n][f][0] + bb0));
                    float v1 = __sinf(W0F * (acc[n][f][1] + bb1));
                    float v2 = __sinf(W0F * (acc[n][f][2] + bb0));
                    float v3 = __sinf(W0F * (acc[n][f][3] + bb1));
                    uint32_t a0 = aoff(r, col);
                    uint32_t a1 = aoff(r + 8, col);
                    *reinterpret_cast<uint32_t*>(smem + OFF_AHI + a0) = pack2(v0, v1);
                    *reinterpret_cast<uint32_t*>(smem + OFF_ALO + a0) = pack2lo(v0, v1);
                    *reinterpret_cast<uint32_t*>(smem + OFF_AHI + a1) = pack2(v2, v3);
                    *reinterpret_cast<uint32_t*>(smem + OFF_ALO + a1) = pack2lo(v2, v3);
                }
            }
            __syncthreads();   // A writes visible before next-layer reads
        } else {
            // final: sine + wf dot (3 outputs), partial per n-quarter
            const float* bl = b123 + 512;
            float p[8][3];
#pragma unroll
            for (int i = 0; i < 8; i++)
#pragma unroll
                for (int o = 0; o < 3; o++) p[i][o] = 0.0f;
#pragma unroll
            for (int n = 0; n < 8; n++) {
#pragma unroll
                for (int f = 0; f < 4; f++) {
                    int col = wn * 64 + n * 8 + q * 2;
                    float bb0 = bl[col], bb1 = bl[col + 1];
                    float v0 = __sinf(W0F * (acc[n][f][0] + bb0));
                    float v1 = __sinf(W0F * (acc[n][f][1] + bb1));
                    float v2 = __sinf(W0F * (acc[n][f][2] + bb0));
                    float v3 = __sinf(W0F * (acc[n][f][3] + bb1));
#pragma unroll
                    for (int o = 0; o < 3; o++) {
                        float wf0 = wfs[o * 256 + col], wf1 = wfs[o * 256 + col + 1];
                        p[f * 2 + 0][o] = fmaf(v0, wf0, fmaf(v1, wf1, p[f * 2 + 0][o]));
                        p[f * 2 + 1][o] = fmaf(v2, wf0, fmaf(v3, wf1, p[f * 2 + 1][o]));
                    }
                }
            }
#pragma unroll
            for (int i = 0; i < 8; i++)
#pragma unroll
                for (int o = 0; o < 3; o++) {
                    p[i][o] += __shfl_xor_sync(0xffffffffu, p[i][o], 1);
                    p[i][o] += __shfl_xor_sync(0xffffffffu, p[i][o], 2);
                }
            if (q == 0) {
#pragma unroll
                for (int f = 0; f < 4; f++)
#pragma unroll
                    for (int pr = 0; pr < 2; pr++) {
                        int r = f * 16 + pr * 8 + rl;   // 0..63
#pragma unroll
                        for (int o = 0; o < 3; o++)
                            pbuf[wn * 192 + r * 3 + o] = p[f * 2 + pr][o];
                    }
            }
            __syncthreads();
            for (int i = tid; i < 192; i += 128) {
                int r = i / 3, o = i - r * 3;
                float v = pbuf[i] + pbuf[192 + i] + pbuf[384 + i] + pbuf[576 + i]
                        + bf[m * 3 + o];
                out[((size_t)(row0 + r) * Mexp + m) * 3 + o] = v;
            }
        }
    }
}

// ---------------------------------------------------------------------------
extern "C" void kernel_launch(void* const* d_in, const int* in_sizes, int n_in,
                              void* d_out, int out_size) {
    (void)in_sizes; (void)n_in; (void)out_size;
    const float* x  = (const float*)d_in[0];
    const float* w0 = (const float*)d_in[1];
    const float* b0 = (const float*)d_in[2];
    const float* w1 = (const float*)d_in[3];
    const float* b1 = (const float*)d_in[4];
    const float* w2 = (const float*)d_in[5];
    const float* b2 = (const float*)d_in[6];
    const float* w3 = (const float*)d_in[7];
    const float* b3 = (const float*)d_in[8];
    const float* wf = (const float*)d_in[9];
    const float* bf = (const float*)d_in[10];
    float* out = (float*)d_out;

    cudaFuncSetAttribute(siren_mma, cudaFuncAttributeMaxDynamicSharedMemorySize,
                         SMEM_TOTAL);

    prep_weights<<<1024, 256>>>(w1, 0);
    prep_weights<<<1024, 256>>>(w2, 1);
    prep_weights<<<1024, 256>>>(w3, 2);

    siren_mma<<<Mexp * (Bdim / 64), 128, SMEM_TOTAL>>>(
        x, w0, b0, b1, b2, b3, wf, bf, out);
}

// round 10
// speedup vs baseline: 1.3858x; 1.3858x over previous
#include <cuda_runtime.h>
#include <cuda_fp16.h>
#include <cstdint>

// ===========================================================================
// PackedSirenExperts via mma.sync m16n8k16 fp16 (portable PTX, compute_103).
// R10: 2-term fp16 split instead of 3-term bf16:
//   A = fp16(A)            (single term; rounding 2^-12 is the error source)
//   W = Wh + Wl (fp16 pair, error 2^-22 -> negligible)
//   D = A*Wh + A*Wl  (fp32 accumulate)  -> 2 MMA passes instead of 3.
// Calibrated error model predicts rel_err ~5.8e-4 (<1e-3).
// Warp tile 64x64 (4 warps = 4 n-quarters); warp-private B staging
// (cp.async own o-quarter, no per-slab CTA barriers); Wh|Wl fused per
// q-block -> one LDS.128 per n per slab. 2 __syncthreads per layer.
// CTA = (expert, 64 rows), 128 thr; 2 CTAs/SM (~79.6 KB smem).
// ===========================================================================

namespace {
constexpr int Mexp = 64;
constexpr int Bdim = 8192;
constexpr float W0F = 30.0f;

constexpr int OFF_A    = 0;          // 64 rows x 512B swizzled fp16 (32K)
constexpr int OFF_WBUF = 32768;      // 2 x 16384 (double-buffered k16 slab)
constexpr int OFF_W0   = 65536;      // 768 f
constexpr int OFF_WF   = 68608;      // 768 f
constexpr int OFF_B0   = 71680;      // 256 f
constexpr int OFF_B123 = 72704;      // 768 f
constexpr int OFF_X    = 75776;      // 192 f
constexpr int OFF_PBUF = 76544;      // 768 f
constexpr int SMEM_TOTAL = 79616;
}

// prepped weights: slab blob = [m][layer*16 + s] of 16KB, laid out as
// 4 o-quarters (wn) x 64 o-rows x 64B; row = 4 q-blocks of 16B:
//   {Wh(k=2q,2q+1), Wh(k=2q+8,2q+9), Wl(k=2q,2q+1), Wl(k=2q+8,2q+9)}  (fp16)
__device__ __align__(16) unsigned char g_wp[(size_t)Mexp * 48 * 16384];

// ---------------------------------------------------------------------------
__device__ __forceinline__ uint32_t smem_u32(const void* p) {
    uint32_t a;
    asm("{ .reg .u64 t; cvta.to.shared.u64 t, %1; cvt.u32.u64 %0, t; }" : "=r"(a) : "l"(p));
    return a;
}
__device__ __forceinline__ void cp16(uint32_t s, const void* g) {
    asm volatile("cp.async.cg.shared.global [%0], [%1], 16;" :: "r"(s), "l"(g));
}
__device__ __forceinline__ void cp_commit() { asm volatile("cp.async.commit_group;"); }
__device__ __forceinline__ void cp_wait0() {
    asm volatile("cp.async.wait_group 0;" ::: "memory");
}
__device__ __forceinline__ uint32_t pack2h(float v0, float v1) {
    __half2 t = __floats2half2_rn(v0, v1);
    return *reinterpret_cast<uint32_t*>(&t);
}
__device__ __forceinline__ uint32_t pack2hlo(float v0, float v1) {
    __half h0 = __float2half_rn(v0);
    __half h1 = __float2half_rn(v1);
    __half2 t = __floats2half2_rn(v0 - __half2float(h0), v1 - __half2float(h1));
    return *reinterpret_cast<uint32_t*>(&t);
}
// A swizzled byte offset: row r (0..63), col k (0..255) fp16
__device__ __forceinline__ uint32_t aoff(int r, int k) {
    return (uint32_t)(r * 512 + ((((k >> 3) ^ (r & 7)) << 4) | ((k & 7) * 2)));
}
__device__ __forceinline__ void mma16816(float* d, const uint32_t* a,
                                         uint32_t b0, uint32_t b1) {
    asm volatile(
        "mma.sync.aligned.m16n8k16.row.col.f32.f16.f16.f32 "
        "{%0,%1,%2,%3}, {%4,%5,%6,%7}, {%8,%9}, {%0,%1,%2,%3};"
        : "+f"(d[0]), "+f"(d[1]), "+f"(d[2]), "+f"(d[3])
        : "r"(a[0]), "r"(a[1]), "r"(a[2]), "r"(a[3]), "r"(b0), "r"(b1));
}
__device__ __forceinline__ void ldsm4(uint32_t* r, uint32_t addr) {
    asm volatile("ldmatrix.sync.aligned.m8n8.x4.shared.b16 {%0,%1,%2,%3}, [%4];"
                 : "=r"(r[0]), "=r"(r[1]), "=r"(r[2]), "=r"(r[3]) : "r"(addr));
}

// ---------------------------------------------------------------------------
// Prep: fp32 W[m][o][i] -> k16-slab blobs, quarter-major, 64B rows,
// Wh|Wl fused per q-block (fp16). One thread per (m, slab, o).
// ---------------------------------------------------------------------------
__global__ void prep_weights(const float* __restrict__ w, int layer) {
    int id = blockIdx.x * blockDim.x + threadIdx.x;   // 262144
    int o = id & 255;
    int s = (id >> 8) & 15;
    int m = id >> 12;
    const float* src = w + ((size_t)m * 256 + o) * 256 + s * 16;
    unsigned char* dst = g_wp + (size_t)(m * 48 + layer * 16 + s) * 16384
                       + (o >> 6) * 4096 + (o & 63) * 64;    // 64B row stride
#pragma unroll
    for (int q = 0; q < 4; q++) {
        float f0 = src[2 * q],     f1 = src[2 * q + 1];
        float f2 = src[2 * q + 8], f3 = src[2 * q + 9];
        uint4 v;
        v.x = pack2h(f0, f1);    v.y = pack2h(f2, f3);
        v.z = pack2hlo(f0, f1);  v.w = pack2hlo(f2, f3);
        *reinterpret_cast<uint4*>(dst + q * 16) = v;
    }
}

// ---------------------------------------------------------------------------
// Main kernel. grid = Mexp*128 = 8192 CTAs (expert-major), 128 threads.
// ---------------------------------------------------------------------------
__global__ void __launch_bounds__(128, 2)
siren_mma(const float* __restrict__ x,
          const float* __restrict__ w0, const float* __restrict__ b0,
          const float* __restrict__ b1, const float* __restrict__ b2,
          const float* __restrict__ b3,
          const float* __restrict__ wf, const float* __restrict__ bf,
          float* __restrict__ out) {
    extern __shared__ __align__(16) unsigned char smem[];
    const uint32_t sb = smem_u32(smem);
    float* w0s  = reinterpret_cast<float*>(smem + OFF_W0);
    float* wfs  = reinterpret_cast<float*>(smem + OFF_WF);
    float* b0s  = reinterpret_cast<float*>(smem + OFF_B0);
    float* b123 = reinterpret_cast<float*>(smem + OFF_B123);
    float* xs   = reinterpret_cast<float*>(smem + OFF_X);
    float* pbuf = reinterpret_cast<float*>(smem + OFF_PBUF);

    const int tid  = threadIdx.x;
    const int lane = tid & 31;
    const int wn   = tid >> 5;         // warp = n-quarter: cols wn*64..+63
    const int rl   = lane >> 2;        // 0..7
    const int q    = lane & 3;         // 0..3
    const int m    = blockIdx.x >> 7;
    const int bt   = blockIdx.x & 127;
    const int row0 = bt * 64;
    const int lrow  = lane & 15;
    const int lhalf = lane >> 4;

    const unsigned char* wpm = g_wp + (size_t)m * 48 * 16384;

    // ---- prefetch slab 0 (own warp quarter: 4KB) ----
    {
        uint32_t dst = sb + OFF_WBUF + (uint32_t)(wn * 4096 + lane * 16);
        const unsigned char* src = wpm + wn * 4096 + lane * 16;
#pragma unroll
        for (int i = 0; i < 8; i++) cp16(dst + i * 512, src + i * 512);
        cp_commit();
    }

    // ---- stage small tensors ----
    for (int i = tid; i < 768; i += 128) w0s[i] = w0[m * 768 + i];
    for (int i = tid; i < 768; i += 128) wfs[i] = wf[m * 768 + i];
    for (int i = tid; i < 256; i += 128) {
        b0s[i]        = b0[m * 256 + i];
        b123[i]       = b1[m * 256 + i];
        b123[256 + i] = b2[m * 256 + i];
        b123[512 + i] = b3[m * 256 + i];
    }
    for (int i = tid; i < 192; i += 128) xs[i] = x[(size_t)row0 * 3 + i];
    __syncthreads();

    // ---- layer 0: warp covers cols [wn*64,+64), all 64 rows ----
    {
        const int cbase = wn * 64;
#pragma unroll 4
        for (int i = 0; i < 64; i++) {
            int pid = i * 32 + lane;
            int r  = pid & 63;
            int c  = cbase + (pid >> 6) * 2;
            float x0 = xs[r * 3], x1 = xs[r * 3 + 1], x2 = xs[r * 3 + 2];
            float p0 = fmaf(x2, w0s[c * 3 + 2], fmaf(x1, w0s[c * 3 + 1],
                       fmaf(x0, w0s[c * 3 + 0], b0s[c])));
            float p1 = fmaf(x2, w0s[c * 3 + 5], fmaf(x1, w0s[c * 3 + 4],
                       fmaf(x0, w0s[c * 3 + 3], b0s[c + 1])));
            float v0 = __sinf(W0F * p0);
            float v1 = __sinf(W0F * p1);
            *reinterpret_cast<uint32_t*>(smem + OFF_A + aoff(r, c)) = pack2h(v0, v1);
        }
    }
    __syncthreads();

    // ---- 3 hidden layers over 48 k16 weight slabs ----
    int t = 0;
#pragma unroll 1
    for (int L = 0; L < 3; L++) {
        float acc[8][4][4];               // [n][f][v]
#pragma unroll
        for (int n = 0; n < 8; n++)
#pragma unroll
            for (int f = 0; f < 4; f++)
#pragma unroll
                for (int v = 0; v < 4; v++) acc[n][f][v] = 0.0f;

        uint32_t ah[4][4];

#pragma unroll 1
        for (int s = 0; s < 16; s++, t++) {
            cp_wait0();
            __syncwarp();
            if (t < 47) {
                uint32_t dst = sb + OFF_WBUF + ((t + 1) & 1) * 16384
                             + (uint32_t)(wn * 4096 + lane * 16);
                const unsigned char* src = wpm + (size_t)(t + 1) * 16384
                                         + wn * 4096 + lane * 16;
#pragma unroll
                for (int i = 0; i < 8; i++) cp16(dst + i * 512, src + i * 512);
                cp_commit();
            }
            const unsigned char* wb = smem + OFF_WBUF + (t & 1) * 16384 + wn * 4096;

            // B fragments: 8 x LDS.128 {Wh.x,Wh.y,Wl.x,Wl.y}, 64B rows
            uint4 bq[8];
#pragma unroll
            for (int n = 0; n < 8; n++)
                bq[n] = *reinterpret_cast<const uint4*>(wb + (n * 8 + rl) * 64 + q * 16);

            // A fragments: f=0..3 via ldmatrix.x4
            {
                int c3 = s * 2 + lhalf;
#pragma unroll
                for (int f = 0; f < 4; f++) {
                    int row = f * 16 + lrow;
                    uint32_t ad = sb + (uint32_t)(row * 512 + ((c3 ^ (row & 7)) << 4));
                    ldsm4(ah[f], ad);
                }
            }

            // pass 1: A * Wh
#pragma unroll
            for (int n = 0; n < 8; n++)
#pragma unroll
                for (int f = 0; f < 4; f++)
                    mma16816(acc[n][f], ah[f], bq[n].x, bq[n].y);
            // pass 2: A * Wl
#pragma unroll
            for (int n = 0; n < 8; n++)
#pragma unroll
                for (int f = 0; f < 4; f++)
                    mma16816(acc[n][f], ah[f], bq[n].z, bq[n].w);
        }

        __syncthreads();   // all warps done reading A before overwrite

        if (L < 2) {
            const float* bl = b123 + L * 256;
#pragma unroll
            for (int n = 0; n < 8; n++) {
#pragma unroll
                for (int f = 0; f < 4; f++) {
                    int r   = f * 16 + rl;
                    int col = wn * 64 + n * 8 + q * 2;
                    float bb0 = bl[col], bb1 = bl[col + 1];
                    float v0 = __sinf(W0F * (acc[n][f][0] + bb0));
                    float v1 = __sinf(W0F * (acc[n][f][1] + bb1));
                    float v2 = __sinf(W0F * (acc[n][f][2] + bb0));
                    float v3 = __sinf(W0F * (acc[n][f][3] + bb1));
                    *reinterpret_cast<uint32_t*>(smem + OFF_A + aoff(r, col))
                        = pack2h(v0, v1);
                    *reinterpret_cast<uint32_t*>(smem + OFF_A + aoff(r + 8, col))
                        = pack2h(v2, v3);
                }
            }
            __syncthreads();   // A writes visible before next-layer reads
        } else {
            // final: sine + wf dot (3 outputs), partial per n-quarter
            const float* bl = b123 + 512;
            float p[8][3];
#pragma unroll
            for (int i = 0; i < 8; i++)
#pragma unroll
                for (int o = 0; o < 3; o++) p[i][o] = 0.0f;
#pragma unroll
            for (int n = 0; n < 8; n++) {
#pragma unroll
                for (int f = 0; f < 4; f++) {
                    int col = wn * 64 + n * 8 + q * 2;
                    float bb0 = bl[col], bb1 = bl[col + 1];
                    float v0 = __sinf(W0F * (acc[n][f][0] + bb0));
                    float v1 = __sinf(W0F * (acc[n][f][1] + bb1));
                    float v2 = __sinf(W0F * (acc[n][f][2] + bb0));
                    float v3 = __sinf(W0F * (acc[n][f][3] + bb1));
#pragma unroll
                    for (int o = 0; o < 3; o++) {
                        float wf0 = wfs[o * 256 + col], wf1 = wfs[o * 256 + col + 1];
                        p[f * 2 + 0][o] = fmaf(v0, wf0, fmaf(v1, wf1, p[f * 2 + 0][o]));
                        p[f * 2 + 1][o] = fmaf(v2, wf0, fmaf(v3, wf1, p[f * 2 + 1][o]));
                    }
                }
            }
#pragma unroll
            for (int i = 0; i < 8; i++)
#pragma unroll
                for (int o = 0; o < 3; o++) {
                    p[i][o] += __shfl_xor_sync(0xffffffffu, p[i][o], 1);
                    p[i][o] += __shfl_xor_sync(0xffffffffu, p[i][o], 2);
                }
            if (q == 0) {
#pragma unroll
                for (int f = 0; f < 4; f++)
#pragma unroll
                    for (int pr = 0; pr < 2; pr++) {
                        int r = f * 16 + pr * 8 + rl;   // 0..63
#pragma unroll
                        for (int o = 0; o < 3; o++)
                            pbuf[wn * 192 + r * 3 + o] = p[f * 2 + pr][o];
                    }
            }
            __syncthreads();
            for (int i = tid; i < 192; i += 128) {
                int r = i / 3, o = i - r * 3;
                float v = pbuf[i] + pbuf[192 + i] + pbuf[384 + i] + pbuf[576 + i]
                        + bf[m * 3 + o];
                out[((size_t)(row0 + r) * Mexp + m) * 3 + o] = v;
            }
        }
    }
}

// ---------------------------------------------------------------------------
extern "C" void kernel_launch(void* const* d_in, const int* in_sizes, int n_in,
                              void* d_out, int out_size) {
    (void)in_sizes; (void)n_in; (void)out_size;
    const float* x  = (const float*)d_in[0];
    const float* w0 = (const float*)d_in[1];
    const float* b0 = (const float*)d_in[2];
    const float* w1 = (const float*)d_in[3];
    const float* b1 = (const float*)d_in[4];
    const float* w2 = (const float*)d_in[5];
    const float* b2 = (const float*)d_in[6];
    const float* w3 = (const float*)d_in[7];
    const float* b3 = (const float*)d_in[8];
    const float* wf = (const float*)d_in[9];
    const float* bf = (const float*)d_in[10];
    float* out = (float*)d_out;

    cudaFuncSetAttribute(siren_mma, cudaFuncAttributeMaxDynamicSharedMemorySize,
                         SMEM_TOTAL);

    prep_weights<<<1024, 256>>>(w1, 0);
    prep_weights<<<1024, 256>>>(w2, 1);
    prep_weights<<<1024, 256>>>(w3, 2);

    siren_mma<<<Mexp * (Bdim / 64), 128, SMEM_TOTAL>>>(
        x, w0, b0, b1, b2, b3, wf, bf, out);
}

// round 11
// speedup vs baseline: 1.8708x; 1.3500x over previous
#include <cuda_runtime.h>
#include <cuda_fp16.h>
#include <cstdint>

// ===========================================================================
// PackedSirenExperts via mma.sync m16n8k16 fp16 (portable PTX, compute_103).
// R11: SINGLE-pass pure fp16 MMA:
//   A = fp16(A), W = fp16(W), D = A*W (fp32 accumulate) -> 1 MMA pass.
// Calibrated error model: A-rounding alone measured 3.69e-4; W-rounding adds
// an independent same-magnitude term -> predicted rel_err ~5.2e-4 < 1e-3.
// Warp tile 64x64 (4 warps = 4 n-quarters); warp-private B staging
// (cp.async own o-quarter, no per-slab CTA barriers); 8KB k16 slabs,
// B fragments via conflict-free LDS.64. 2 __syncthreads per layer.
// CTA = (expert, 64 rows), 128 thr; 2 CTAs/SM (~62 KB smem).
// ===========================================================================

namespace {
constexpr int Mexp = 64;
constexpr int Bdim = 8192;
constexpr float W0F = 30.0f;

constexpr int OFF_A    = 0;          // 64 rows x 512B swizzled fp16 (32K)
constexpr int OFF_WBUF = 32768;      // 2 x 8192 (double-buffered k16 slab)
constexpr int OFF_W0   = 49152;      // 768 f
constexpr int OFF_WF   = 52224;      // 768 f
constexpr int OFF_B0   = 55296;      // 256 f
constexpr int OFF_B123 = 56320;      // 768 f
constexpr int OFF_X    = 59392;      // 192 f
constexpr int OFF_PBUF = 60160;      // 768 f
constexpr int SMEM_TOTAL = 63232;
}

// prepped weights: slab blob = [m][layer*16 + s] of 8KB, laid out as
// 4 o-quarters (wn) x 64 o-rows x 32B; row = 4 q-words (uint2):
//   {W(k=2q,2q+1), W(k=2q+8,2q+9)}  (fp16)
__device__ __align__(16) unsigned char g_wp[(size_t)Mexp * 48 * 8192];

// ---------------------------------------------------------------------------
__device__ __forceinline__ uint32_t smem_u32(const void* p) {
    uint32_t a;
    asm("{ .reg .u64 t; cvta.to.shared.u64 t, %1; cvt.u32.u64 %0, t; }" : "=r"(a) : "l"(p));
    return a;
}
__device__ __forceinline__ void cp16(uint32_t s, const void* g) {
    asm volatile("cp.async.cg.shared.global [%0], [%1], 16;" :: "r"(s), "l"(g));
}
__device__ __forceinline__ void cp_commit() { asm volatile("cp.async.commit_group;"); }
__device__ __forceinline__ void cp_wait0() {
    asm volatile("cp.async.wait_group 0;" ::: "memory");
}
__device__ __forceinline__ uint32_t pack2h(float v0, float v1) {
    __half2 t = __floats2half2_rn(v0, v1);
    return *reinterpret_cast<uint32_t*>(&t);
}
// A swizzled byte offset: row r (0..63), col k (0..255) fp16
__device__ __forceinline__ uint32_t aoff(int r, int k) {
    return (uint32_t)(r * 512 + ((((k >> 3) ^ (r & 7)) << 4) | ((k & 7) * 2)));
}
__device__ __forceinline__ void mma16816(float* d, const uint32_t* a,
                                         uint32_t b0, uint32_t b1) {
    asm volatile(
        "mma.sync.aligned.m16n8k16.row.col.f32.f16.f16.f32 "
        "{%0,%1,%2,%3}, {%4,%5,%6,%7}, {%8,%9}, {%0,%1,%2,%3};"
        : "+f"(d[0]), "+f"(d[1]), "+f"(d[2]), "+f"(d[3])
        : "r"(a[0]), "r"(a[1]), "r"(a[2]), "r"(a[3]), "r"(b0), "r"(b1));
}
__device__ __forceinline__ void ldsm4(uint32_t* r, uint32_t addr) {
    asm volatile("ldmatrix.sync.aligned.m8n8.x4.shared.b16 {%0,%1,%2,%3}, [%4];"
                 : "=r"(r[0]), "=r"(r[1]), "=r"(r[2]), "=r"(r[3]) : "r"(addr));
}

// ---------------------------------------------------------------------------
// Prep: fp32 W[m][o][i] -> k16-slab blobs (8KB), quarter-major, 32B rows.
// One thread per (m, slab, o).
// ---------------------------------------------------------------------------
__global__ void prep_weights(const float* __restrict__ w, int layer) {
    int id = blockIdx.x * blockDim.x + threadIdx.x;   // 262144
    int o = id & 255;
    int s = (id >> 8) & 15;
    int m = id >> 12;
    const float* src = w + ((size_t)m * 256 + o) * 256 + s * 16;
    unsigned char* dst = g_wp + (size_t)(m * 48 + layer * 16 + s) * 8192
                       + (o >> 6) * 2048 + (o & 63) * 32;    // 32B row stride
#pragma unroll
    for (int q = 0; q < 4; q++) {
        float f0 = src[2 * q],     f1 = src[2 * q + 1];
        float f2 = src[2 * q + 8], f3 = src[2 * q + 9];
        uint2 v;
        v.x = pack2h(f0, f1);
        v.y = pack2h(f2, f3);
        *reinterpret_cast<uint2*>(dst + q * 8) = v;
    }
}

// ---------------------------------------------------------------------------
// Main kernel. grid = Mexp*128 = 8192 CTAs (expert-major), 128 threads.
// ---------------------------------------------------------------------------
__global__ void __launch_bounds__(128, 2)
siren_mma(const float* __restrict__ x,
          const float* __restrict__ w0, const float* __restrict__ b0,
          const float* __restrict__ b1, const float* __restrict__ b2,
          const float* __restrict__ b3,
          const float* __restrict__ wf, const float* __restrict__ bf,
          float* __restrict__ out) {
    extern __shared__ __align__(16) unsigned char smem[];
    const uint32_t sb = smem_u32(smem);
    float* w0s  = reinterpret_cast<float*>(smem + OFF_W0);
    float* wfs  = reinterpret_cast<float*>(smem + OFF_WF);
    float* b0s  = reinterpret_cast<float*>(smem + OFF_B0);
    float* b123 = reinterpret_cast<float*>(smem + OFF_B123);
    float* xs   = reinterpret_cast<float*>(smem + OFF_X);
    float* pbuf = reinterpret_cast<float*>(smem + OFF_PBUF);

    const int tid  = threadIdx.x;
    const int lane = tid & 31;
    const int wn   = tid >> 5;         // warp = n-quarter: cols wn*64..+63
    const int rl   = lane >> 2;        // 0..7
    const int q    = lane & 3;         // 0..3
    const int m    = blockIdx.x >> 7;
    const int bt   = blockIdx.x & 127;
    const int row0 = bt * 64;
    const int lrow  = lane & 15;
    const int lhalf = lane >> 4;

    const unsigned char* wpm = g_wp + (size_t)m * 48 * 8192;

    // ---- prefetch slab 0 (own warp quarter: 2KB) ----
    {
        uint32_t dst = sb + OFF_WBUF + (uint32_t)(wn * 2048 + lane * 16);
        const unsigned char* src = wpm + wn * 2048 + lane * 16;
#pragma unroll
        for (int i = 0; i < 4; i++) cp16(dst + i * 512, src + i * 512);
        cp_commit();
    }

    // ---- stage small tensors ----
    for (int i = tid; i < 768; i += 128) w0s[i] = w0[m * 768 + i];
    for (int i = tid; i < 768; i += 128) wfs[i] = wf[m * 768 + i];
    for (int i = tid; i < 256; i += 128) {
        b0s[i]        = b0[m * 256 + i];
        b123[i]       = b1[m * 256 + i];
        b123[256 + i] = b2[m * 256 + i];
        b123[512 + i] = b3[m * 256 + i];
    }
    for (int i = tid; i < 192; i += 128) xs[i] = x[(size_t)row0 * 3 + i];
    __syncthreads();

    // ---- layer 0: warp covers cols [wn*64,+64), all 64 rows ----
    {
        const int cbase = wn * 64;
#pragma unroll 4
        for (int i = 0; i < 64; i++) {
            int pid = i * 32 + lane;
            int r  = pid & 63;
            int c  = cbase + (pid >> 6) * 2;
            float x0 = xs[r * 3], x1 = xs[r * 3 + 1], x2 = xs[r * 3 + 2];
            float p0 = fmaf(x2, w0s[c * 3 + 2], fmaf(x1, w0s[c * 3 + 1],
                       fmaf(x0, w0s[c * 3 + 0], b0s[c])));
            float p1 = fmaf(x2, w0s[c * 3 + 5], fmaf(x1, w0s[c * 3 + 4],
                       fmaf(x0, w0s[c * 3 + 3], b0s[c + 1])));
            float v0 = __sinf(W0F * p0);
            float v1 = __sinf(W0F * p1);
            *reinterpret_cast<uint32_t*>(smem + OFF_A + aoff(r, c)) = pack2h(v0, v1);
        }
    }
    __syncthreads();

    // ---- 3 hidden layers over 48 k16 weight slabs ----
    int t = 0;
#pragma unroll 1
    for (int L = 0; L < 3; L++) {
        float acc[8][4][4];               // [n][f][v]
#pragma unroll
        for (int n = 0; n < 8; n++)
#pragma unroll
            for (int f = 0; f < 4; f++)
#pragma unroll
                for (int v = 0; v < 4; v++) acc[n][f][v] = 0.0f;

        uint32_t ah[4][4];

#pragma unroll 1
        for (int s = 0; s < 16; s++, t++) {
            cp_wait0();
            __syncwarp();
            if (t < 47) {
                uint32_t dst = sb + OFF_WBUF + ((t + 1) & 1) * 8192
                             + (uint32_t)(wn * 2048 + lane * 16);
                const unsigned char* src = wpm + (size_t)(t + 1) * 8192
                                         + wn * 2048 + lane * 16;
#pragma unroll
                for (int i = 0; i < 4; i++) cp16(dst + i * 512, src + i * 512);
                cp_commit();
            }
            const unsigned char* wb = smem + OFF_WBUF + (t & 1) * 8192 + wn * 2048;

            // B fragments: 8 x LDS.64 {W.x, W.y}, 32B rows (conflict-free)
            uint2 bq[8];
#pragma unroll
            for (int n = 0; n < 8; n++)
                bq[n] = *reinterpret_cast<const uint2*>(wb + (n * 8 + rl) * 32 + q * 8);

            // A fragments: f=0..3 via ldmatrix.x4
            {
                int c3 = s * 2 + lhalf;
#pragma unroll
                for (int f = 0; f < 4; f++) {
                    int row = f * 16 + lrow;
                    uint32_t ad = sb + (uint32_t)(row * 512 + ((c3 ^ (row & 7)) << 4));
                    ldsm4(ah[f], ad);
                }
            }

            // single pass: A * W
#pragma unroll
            for (int n = 0; n < 8; n++)
#pragma unroll
                for (int f = 0; f < 4; f++)
                    mma16816(acc[n][f], ah[f], bq[n].x, bq[n].y);
        }

        __syncthreads();   // all warps done reading A before overwrite

        if (L < 2) {
            const float* bl = b123 + L * 256;
#pragma unroll
            for (int n = 0; n < 8; n++) {
#pragma unroll
                for (int f = 0; f < 4; f++) {
                    int r   = f * 16 + rl;
                    int col = wn * 64 + n * 8 + q * 2;
                    float bb0 = bl[col], bb1 = bl[col + 1];
                    float v0 = __sinf(W0F * (acc[n][f][0] + bb0));
                    float v1 = __sinf(W0F * (acc[n][f][1] + bb1));
                    float v2 = __sinf(W0F * (acc[n][f][2] + bb0));
                    float v3 = __sinf(W0F * (acc[n][f][3] + bb1));
                    *reinterpret_cast<uint32_t*>(smem + OFF_A + aoff(r, col))
                        = pack2h(v0, v1);
                    *reinterpret_cast<uint32_t*>(smem + OFF_A + aoff(r + 8, col))
                        = pack2h(v2, v3);
                }
            }
            __syncthreads();   // A writes visible before next-layer reads
        } else {
            // final: sine + wf dot (3 outputs), partial per n-quarter
            const float* bl = b123 + 512;
            float p[8][3];
#pragma unroll
            for (int i = 0; i < 8; i++)
#pragma unroll
                for (int o = 0; o < 3; o++) p[i][o] = 0.0f;
#pragma unroll
            for (int n = 0; n < 8; n++) {
#pragma unroll
                for (int f = 0; f < 4; f++) {
                    int col = wn * 64 + n * 8 + q * 2;
                    float bb0 = bl[col], bb1 = bl[col + 1];
                    float v0 = __sinf(W0F * (acc[n][f][0] + bb0));
                    float v1 = __sinf(W0F * (acc[n][f][1] + bb1));
                    float v2 = __sinf(W0F * (acc[n][f][2] + bb0));
                    float v3 = __sinf(W0F * (acc[n][f][3] + bb1));
#pragma unroll
                    for (int o = 0; o < 3; o++) {
                        float wf0 = wfs[o * 256 + col], wf1 = wfs[o * 256 + col + 1];
                        p[f * 2 + 0][o] = fmaf(v0, wf0, fmaf(v1, wf1, p[f * 2 + 0][o]));
                        p[f * 2 + 1][o] = fmaf(v2, wf0, fmaf(v3, wf1, p[f * 2 + 1][o]));
                    }
                }
            }
#pragma unroll
            for (int i = 0; i < 8; i++)
#pragma unroll
                for (int o = 0; o < 3; o++) {
                    p[i][o] += __shfl_xor_sync(0xffffffffu, p[i][o], 1);
                    p[i][o] += __shfl_xor_sync(0xffffffffu, p[i][o], 2);
                }
            if (q == 0) {
#pragma unroll
                for (int f = 0; f < 4; f++)
#pragma unroll
                    for (int pr = 0; pr < 2; pr++) {
                        int r = f * 16 + pr * 8 + rl;   // 0..63
#pragma unroll
                        for (int o = 0; o < 3; o++)
                            pbuf[wn * 192 + r * 3 + o] = p[f * 2 + pr][o];
                    }
            }
            __syncthreads();
            for (int i = tid; i < 192; i += 128) {
                int r = i / 3, o = i - r * 3;
                float v = pbuf[i] + pbuf[192 + i] + pbuf[384 + i] + pbuf[576 + i]
                        + bf[m * 3 + o];
                out[((size_t)(row0 + r) * Mexp + m) * 3 + o] = v;
            }
        }
    }
}

// ---------------------------------------------------------------------------
extern "C" void kernel_launch(void* const* d_in, const int* in_sizes, int n_in,
                              void* d_out, int out_size) {
    (void)in_sizes; (void)n_in; (void)out_size;
    const float* x  = (const float*)d_in[0];
    const float* w0 = (const float*)d_in[1];
    const float* b0 = (const float*)d_in[2];
    const float* w1 = (const float*)d_in[3];
    const float* b1 = (const float*)d_in[4];
    const float* w2 = (const float*)d_in[5];
    const float* b2 = (const float*)d_in[6];
    const float* w3 = (const float*)d_in[7];
    const float* b3 = (const float*)d_in[8];
    const float* wf = (const float*)d_in[9];
    const float* bf = (const float*)d_in[10];
    float* out = (float*)d_out;

    cudaFuncSetAttribute(siren_mma, cudaFuncAttributeMaxDynamicSharedMemorySize,
                         SMEM_TOTAL);

    prep_weights<<<1024, 256>>>(w1, 0);
    prep_weights<<<1024, 256>>>(w2, 1);
    prep_weights<<<1024, 256>>>(w3, 2);

    siren_mma<<<Mexp * (Bdim / 64), 128, SMEM_TOTAL>>>(
        x, w0, b0, b1, b2, b3, wf, bf, out);
}

// round 12
// speedup vs baseline: 2.2301x; 1.1920x over previous
#include <cuda_runtime.h>
#include <cuda_fp16.h>
#include <cstdint>

// ===========================================================================
// PackedSirenExperts via mma.sync m16n8k16 fp16 (portable PTX, compute_103).
// R12 = R11 numerics (single-pass pure fp16, rel_err 5.97e-4) with 8 warps
// per CTA (256 thr), warp tile 64x32 (acc 64 regs):
//   - 16 warps/SM (4/SMSP): 2x latency hiding for MMA + epilogue chains
//   - per-warp epilogue halves; per-warp B staging 1KB/slab (warp-private,
//     no per-slab CTA barriers; cp.async.wait_group 0 + __syncwarp only)
// CTA = (expert, 64 rows); 2 CTAs/SM (~66 KB smem, <=128 regs).
// ===========================================================================

namespace {
constexpr int Mexp = 64;
constexpr int Bdim = 8192;
constexpr float W0F = 30.0f;

constexpr int OFF_A    = 0;          // 64 rows x 512B swizzled fp16 (32K)
constexpr int OFF_WBUF = 32768;      // 2 x 8192 (double-buffered k16 slab)
constexpr int OFF_W0   = 49152;      // 768 f
constexpr int OFF_WF   = 52224;      // 768 f
constexpr int OFF_B0   = 55296;      // 256 f
constexpr int OFF_B123 = 56320;      // 768 f
constexpr int OFF_X    = 59392;      // 192 f
constexpr int OFF_PBUF = 60160;      // 1536 f (8 eighths x 64 rows x 3)
constexpr int SMEM_TOTAL = 66304;
}

// prepped weights: slab blob = [m][layer*16 + s] of 8KB, laid out as
// 8 o-eighths (wn) x 32 o-rows x 32B; row = 4 q-words (uint2):
//   {W(k=2q,2q+1), W(k=2q+8,2q+9)}  (fp16)
__device__ __align__(16) unsigned char g_wp[(size_t)Mexp * 48 * 8192];

// ---------------------------------------------------------------------------
__device__ __forceinline__ uint32_t smem_u32(const void* p) {
    uint32_t a;
    asm("{ .reg .u64 t; cvta.to.shared.u64 t, %1; cvt.u32.u64 %0, t; }" : "=r"(a) : "l"(p));
    return a;
}
__device__ __forceinline__ void cp16(uint32_t s, const void* g) {
    asm volatile("cp.async.cg.shared.global [%0], [%1], 16;" :: "r"(s), "l"(g));
}
__device__ __forceinline__ void cp_commit() { asm volatile("cp.async.commit_group;"); }
__device__ __forceinline__ void cp_wait0() {
    asm volatile("cp.async.wait_group 0;" ::: "memory");
}
__device__ __forceinline__ uint32_t pack2h(float v0, float v1) {
    __half2 t = __floats2half2_rn(v0, v1);
    return *reinterpret_cast<uint32_t*>(&t);
}
// A swizzled byte offset: row r (0..63), col k (0..255) fp16
__device__ __forceinline__ uint32_t aoff(int r, int k) {
    return (uint32_t)(r * 512 + ((((k >> 3) ^ (r & 7)) << 4) | ((k & 7) * 2)));
}
__device__ __forceinline__ void mma16816(float* d, const uint32_t* a,
                                         uint32_t b0, uint32_t b1) {
    asm volatile(
        "mma.sync.aligned.m16n8k16.row.col.f32.f16.f16.f32 "
        "{%0,%1,%2,%3}, {%4,%5,%6,%7}, {%8,%9}, {%0,%1,%2,%3};"
        : "+f"(d[0]), "+f"(d[1]), "+f"(d[2]), "+f"(d[3])
        : "r"(a[0]), "r"(a[1]), "r"(a[2]), "r"(a[3]), "r"(b0), "r"(b1));
}
__device__ __forceinline__ void ldsm4(uint32_t* r, uint32_t addr) {
    asm volatile("ldmatrix.sync.aligned.m8n8.x4.shared.b16 {%0,%1,%2,%3}, [%4];"
                 : "=r"(r[0]), "=r"(r[1]), "=r"(r[2]), "=r"(r[3]) : "r"(addr));
}

// ---------------------------------------------------------------------------
// Prep: fp32 W[m][o][i] -> k16-slab blobs (8KB), eighth-major, 32B rows.
// One thread per (m, slab, o).
// ---------------------------------------------------------------------------
__global__ void prep_weights(const float* __restrict__ w, int layer) {
    int id = blockIdx.x * blockDim.x + threadIdx.x;   // 262144
    int o = id & 255;
    int s = (id >> 8) & 15;
    int m = id >> 12;
    const float* src = w + ((size_t)m * 256 + o) * 256 + s * 16;
    unsigned char* dst = g_wp + (size_t)(m * 48 + layer * 16 + s) * 8192
                       + (o >> 5) * 1024 + (o & 31) * 32;    // 32B row stride
#pragma unroll
    for (int q = 0; q < 4; q++) {
        float f0 = src[2 * q],     f1 = src[2 * q + 1];
        float f2 = src[2 * q + 8], f3 = src[2 * q + 9];
        uint2 v;
        v.x = pack2h(f0, f1);
        v.y = pack2h(f2, f3);
        *reinterpret_cast<uint2*>(dst + q * 8) = v;
    }
}

// ---------------------------------------------------------------------------
// Main kernel. grid = Mexp*128 = 8192 CTAs (expert-major), 256 threads.
// ---------------------------------------------------------------------------
__global__ void __launch_bounds__(256, 2)
siren_mma(const float* __restrict__ x,
          const float* __restrict__ w0, const float* __restrict__ b0,
          const float* __restrict__ b1, const float* __restrict__ b2,
          const float* __restrict__ b3,
          const float* __restrict__ wf, const float* __restrict__ bf,
          float* __restrict__ out) {
    extern __shared__ __align__(16) unsigned char smem[];
    const uint32_t sb = smem_u32(smem);
    float* w0s  = reinterpret_cast<float*>(smem + OFF_W0);
    float* wfs  = reinterpret_cast<float*>(smem + OFF_WF);
    float* b0s  = reinterpret_cast<float*>(smem + OFF_B0);
    float* b123 = reinterpret_cast<float*>(smem + OFF_B123);
    float* xs   = reinterpret_cast<float*>(smem + OFF_X);
    float* pbuf = reinterpret_cast<float*>(smem + OFF_PBUF);

    const int tid  = threadIdx.x;
    const int lane = tid & 31;
    const int wn   = tid >> 5;         // warp = n-eighth: cols wn*32..+31
    const int rl   = lane >> 2;        // 0..7
    const int q    = lane & 3;         // 0..3
    const int m    = blockIdx.x >> 7;
    const int bt   = blockIdx.x & 127;
    const int row0 = bt * 64;
    const int lrow  = lane & 15;
    const int lhalf = lane >> 4;

    const unsigned char* wpm = g_wp + (size_t)m * 48 * 8192;

    // ---- prefetch slab 0 (own warp eighth: 1KB) ----
    {
        uint32_t dst = sb + OFF_WBUF + (uint32_t)(wn * 1024 + lane * 16);
        const unsigned char* src = wpm + wn * 1024 + lane * 16;
        cp16(dst, src);
        cp16(dst + 512, src + 512);
        cp_commit();
    }

    // ---- stage small tensors ----
    for (int i = tid; i < 768; i += 256) w0s[i] = w0[m * 768 + i];
    for (int i = tid; i < 768; i += 256) wfs[i] = wf[m * 768 + i];
    if (tid < 256) {
        b0s[tid]        = b0[m * 256 + tid];
        b123[tid]       = b1[m * 256 + tid];
        b123[256 + tid] = b2[m * 256 + tid];
        b123[512 + tid] = b3[m * 256 + tid];
    }
    if (tid < 192) xs[tid] = x[(size_t)row0 * 3 + tid];
    __syncthreads();

    // ---- layer 0: 8192 (row, col-pair) tasks over 256 threads ----
    {
#pragma unroll 4
        for (int i = 0; i < 32; i++) {
            int pid = i * 256 + tid;
            int r = pid & 63;
            int c = (pid >> 6) * 2;
            float x0 = xs[r * 3], x1 = xs[r * 3 + 1], x2 = xs[r * 3 + 2];
            float p0 = fmaf(x2, w0s[c * 3 + 2], fmaf(x1, w0s[c * 3 + 1],
                       fmaf(x0, w0s[c * 3 + 0], b0s[c])));
            float p1 = fmaf(x2, w0s[c * 3 + 5], fmaf(x1, w0s[c * 3 + 4],
                       fmaf(x0, w0s[c * 3 + 3], b0s[c + 1])));
            float v0 = __sinf(W0F * p0);
            float v1 = __sinf(W0F * p1);
            *reinterpret_cast<uint32_t*>(smem + OFF_A + aoff(r, c)) = pack2h(v0, v1);
        }
    }
    __syncthreads();

    // ---- 3 hidden layers over 48 k16 weight slabs ----
    int t = 0;
#pragma unroll 1
    for (int L = 0; L < 3; L++) {
        float acc[4][4][4];               // [n][f][v]
#pragma unroll
        for (int n = 0; n < 4; n++)
#pragma unroll
            for (int f = 0; f < 4; f++)
#pragma unroll
                for (int v = 0; v < 4; v++) acc[n][f][v] = 0.0f;

        uint32_t ah[4][4];

#pragma unroll 1
        for (int s = 0; s < 16; s++, t++) {
            cp_wait0();
            __syncwarp();
            if (t < 47) {
                uint32_t dst = sb + OFF_WBUF + ((t + 1) & 1) * 8192
                             + (uint32_t)(wn * 1024 + lane * 16);
                const unsigned char* src = wpm + (size_t)(t + 1) * 8192
                                         + wn * 1024 + lane * 16;
                cp16(dst, src);
                cp16(dst + 512, src + 512);
                cp_commit();
            }
            const unsigned char* wb = smem + OFF_WBUF + (t & 1) * 8192 + wn * 1024;

            // B fragments: 4 x LDS.64 {W.x, W.y}, 32B rows (conflict-free)
            uint2 bq[4];
#pragma unroll
            for (int n = 0; n < 4; n++)
                bq[n] = *reinterpret_cast<const uint2*>(wb + (n * 8 + rl) * 32 + q * 8);

            // A fragments: f=0..3 via ldmatrix.x4
            {
                int c3 = s * 2 + lhalf;
#pragma unroll
                for (int f = 0; f < 4; f++) {
                    int row = f * 16 + lrow;
                    uint32_t ad = sb + (uint32_t)(row * 512 + ((c3 ^ (row & 7)) << 4));
                    ldsm4(ah[f], ad);
                }
            }

            // single pass: A * W
#pragma unroll
            for (int n = 0; n < 4; n++)
#pragma unroll
                for (int f = 0; f < 4; f++)
                    mma16816(acc[n][f], ah[f], bq[n].x, bq[n].y);
        }

        __syncthreads();   // all warps done reading A before overwrite

        if (L < 2) {
            const float* bl = b123 + L * 256;
#pragma unroll
            for (int n = 0; n < 4; n++) {
#pragma unroll
                for (int f = 0; f < 4; f++) {
                    int r   = f * 16 + rl;
                    int col = wn * 32 + n * 8 + q * 2;
                    float bb0 = bl[col], bb1 = bl[col + 1];
                    float v0 = __sinf(W0F * (acc[n][f][0] + bb0));
                    float v1 = __sinf(W0F * (acc[n][f][1] + bb1));
                    float v2 = __sinf(W0F * (acc[n][f][2] + bb0));
                    float v3 = __sinf(W0F * (acc[n][f][3] + bb1));
                    *reinterpret_cast<uint32_t*>(smem + OFF_A + aoff(r, col))
                        = pack2h(v0, v1);
                    *reinterpret_cast<uint32_t*>(smem + OFF_A + aoff(r + 8, col))
                        = pack2h(v2, v3);
                }
            }
            __syncthreads();   // A writes visible before next-layer reads
        } else {
            // final: sine + wf dot (3 outputs), partial per n-eighth
            const float* bl = b123 + 512;
            float p[8][3];
#pragma unroll
            for (int i = 0; i < 8; i++)
#pragma unroll
                for (int o = 0; o < 3; o++) p[i][o] = 0.0f;
#pragma unroll
            for (int n = 0; n < 4; n++) {
#pragma unroll
                for (int f = 0; f < 4; f++) {
                    int col = wn * 32 + n * 8 + q * 2;
                    float bb0 = bl[col], bb1 = bl[col + 1];
                    float v0 = __sinf(W0F * (acc[n][f][0] + bb0));
                    float v1 = __sinf(W0F * (acc[n][f][1] + bb1));
                    float v2 = __sinf(W0F * (acc[n][f][2] + bb0));
                    float v3 = __sinf(W0F * (acc[n][f][3] + bb1));
#pragma unroll
                    for (int o = 0; o < 3; o++) {
                        float wf0 = wfs[o * 256 + col], wf1 = wfs[o * 256 + col + 1];
                        p[f * 2 + 0][o] = fmaf(v0, wf0, fmaf(v1, wf1, p[f * 2 + 0][o]));
                        p[f * 2 + 1][o] = fmaf(v2, wf0, fmaf(v3, wf1, p[f * 2 + 1][o]));
                    }
                }
            }
#pragma unroll
            for (int i = 0; i < 8; i++)
#pragma unroll
                for (int o = 0; o < 3; o++) {
                    p[i][o] += __shfl_xor_sync(0xffffffffu, p[i][o], 1);
                    p[i][o] += __shfl_xor_sync(0xffffffffu, p[i][o], 2);
                }
            if (q == 0) {
#pragma unroll
                for (int f = 0; f < 4; f++)
#pragma unroll
                    for (int pr = 0; pr < 2; pr++) {
                        int r = f * 16 + pr * 8 + rl;   // 0..63
#pragma unroll
                        for (int o = 0; o < 3; o++)
                            pbuf[wn * 192 + r * 3 + o] = p[f * 2 + pr][o];
                    }
            }
            __syncthreads();
            if (tid < 192) {
                int r = tid / 3, o = tid - r * 3;
                float v = bf[m * 3 + o];
#pragma unroll
                for (int w8 = 0; w8 < 8; w8++) v += pbuf[w8 * 192 + tid];
                out[((size_t)(row0 + r) * Mexp + m) * 3 + o] = v;
            }
        }
    }
}

// ---------------------------------------------------------------------------
extern "C" void kernel_launch(void* const* d_in, const int* in_sizes, int n_in,
                              void* d_out, int out_size) {
    (void)in_sizes; (void)n_in; (void)out_size;
    const float* x  = (const float*)d_in[0];
    const float* w0 = (const float*)d_in[1];
    const float* b0 = (const float*)d_in[2];
    const float* w1 = (const float*)d_in[3];
    const float* b1 = (const float*)d_in[4];
    const float* w2 = (const float*)d_in[5];
    const float* b2 = (const float*)d_in[6];
    const float* w3 = (const float*)d_in[7];
    const float* b3 = (const float*)d_in[8];
    const float* wf = (const float*)d_in[9];
    const float* bf = (const float*)d_in[10];
    float* out = (float*)d_out;

    cudaFuncSetAttribute(siren_mma, cudaFuncAttributeMaxDynamicSharedMemorySize,
                         SMEM_TOTAL);

    prep_weights<<<1024, 256>>>(w1, 0);
    prep_weights<<<1024, 256>>>(w2, 1);
    prep_weights<<<1024, 256>>>(w3, 2);

    siren_mma<<<Mexp * (Bdim / 64), 256, SMEM_TOTAL>>>(
        x, w0, b0, b1, b2, b3, wf, bf, out);
}